// round 3
// baseline (speedup 1.0000x reference)
#include <cuda_runtime.h>
#include <cuda_bf16.h>

// Erosion (min filter) k=18, SAME (pad_lo=8, pad_hi=9), on y = x*0.5+0.5.
// NCHW (32,3,512,512) fp32 = 96 planes of 512x512.
//
// Streaming fused separable min filter:
//  - Block = full-width (512 cols) x 128-row strip, 8 chunks of 16 rows.
//  - Vertical pass: thread-per-column van Herk; 17-row hold window carried in
//    registers across chunks -> only 16 new gmem rows per chunk (1.13x halo).
//  - Horizontal pass: per 16-output chunk, 9x LDS.128 (36 floats, 33 used),
//    van Herk sweeps in registers, float4 coalesced stores.
//  - smem stride 540: float4-aligned, conflict-free LDS.128 (112B row stagger).
//  - 0.5x+0.5 is monotone -> applied once per output at the store.

#define W 512
#define H 512
#define CHUNK 16
#define NCHUNKS 8
#define ROWSPB (CHUNK * NCHUNKS)   // 128 rows per block
#define STRIDE 540                 // smem row stride (elements)
#define NTHREADS 512

__global__ __launch_bounds__(NTHREADS, 2)
void erode18_kernel(const float* __restrict__ x, float* __restrict__ out) {
    __shared__ float s_v[CHUNK * STRIDE];   // 34,560 B

    const int tid = threadIdx.x;
    const int rowBase = blockIdx.x * ROWSPB;       // 0,128,256,384
    const long plane = (long)blockIdx.y * (W * H); // 96 planes
    const float INF = __int_as_float(0x7f800000);

    // ---- one-time +inf column pads: smem idx 0..7 (cols -8..-1) and
    //      520..528 (cols 512..520), all 16 rows ----
    if (tid < CHUNK * 17) {
        int r = tid / 17;
        int j = tid - r * 17;
        int idx = (j < 8) ? j : (512 + j);   // 0..7 or 520..528
        s_v[r * STRIDE + idx] = INF;
    }

    const float* colp = x + plane + tid;    // this thread's column

    // ---- warm-up: hold rows rowBase-8 .. rowBase+8 (17 rows) ----
    float hold[17];
    #pragma unroll
    for (int i = 0; i < 17; ++i) {
        int gr = rowBase - 8 + i;
        hold[i] = ((unsigned)gr < (unsigned)H) ? colp[(long)gr * W] : INF;
    }

    const int hr = tid >> 5;     // phase-H: row 0..15 (warp-uniform)
    const int hq = tid & 31;     // phase-H: 16-col chunk 0..31
    const float* rp = s_v + hr * STRIDE + hq * 16;

    for (int c = 0; c < NCHUNKS; ++c) {
        const int b = rowBase + c * CHUNK;   // first output row of chunk

        // ---- Phase V: load 16 new rows, vertical min-18 via van Herk ----
        float nv[16];
        #pragma unroll
        for (int i = 0; i < 16; ++i) {
            int gr = b + 9 + i;
            nv[i] = ((unsigned)gr < (unsigned)H) ? colp[(long)gr * W] : INF;
        }
        // window positions 0..32 = rows b-8..b+24 ; pos<17 -> hold, pos>=17 -> nv
        float S[16];
        {
            float s = nv[0];                     // pos 17
            #pragma unroll
            for (int i = 16; i >= 0; --i) {      // suffix: S[o] = min(pos o..17)
                s = fminf(s, hold[i]);
                if (i <= 15) S[i] = s;
            }
        }
        s_v[0 * STRIDE + 8 + tid] = S[0];
        {
            float p = nv[1];                     // prefix: pos 18..o+17 = nv[1..o]
            s_v[1 * STRIDE + 8 + tid] = fminf(S[1], p);
            #pragma unroll
            for (int o = 2; o <= 15; ++o) {
                p = fminf(p, nv[o]);
                s_v[o * STRIDE + 8 + tid] = fminf(S[o], p);
            }
        }
        // rotate hold window: next chunk holds rows b+8..b+24 = pos 16..32
        hold[0] = hold[16];
        #pragma unroll
        for (int i = 0; i < 16; ++i) hold[i + 1] = nv[i];

        __syncthreads();

        // ---- Phase H: horizontal min-18 from smem (9x LDS.128), f4 stores ----
        {
            float v[36];
            #pragma unroll
            for (int j = 0; j < 9; ++j) {
                float4 t4 = *(const float4*)(rp + 4 * j);
                v[4 * j + 0] = t4.x; v[4 * j + 1] = t4.y;
                v[4 * j + 2] = t4.z; v[4 * j + 3] = t4.w;
            }
            float Sh[16];
            {
                float s = v[17];
                #pragma unroll
                for (int i = 16; i >= 0; --i) {
                    s = fminf(s, v[i]);
                    if (i <= 15) Sh[i] = s;
                }
            }
            float ov[16];
            ov[0] = Sh[0];
            {
                float p = v[18];
                ov[1] = fminf(Sh[1], p);
                #pragma unroll
                for (int o = 2; o <= 15; ++o) {
                    p = fminf(p, v[o + 17]);
                    ov[o] = fminf(Sh[o], p);
                }
            }
            float4* o4 = (float4*)(out + plane + (long)(b + hr) * W + hq * 16);
            #pragma unroll
            for (int g = 0; g < 4; ++g) {
                o4[g] = make_float4(fmaf(ov[4*g+0], 0.5f, 0.5f),
                                    fmaf(ov[4*g+1], 0.5f, 0.5f),
                                    fmaf(ov[4*g+2], 0.5f, 0.5f),
                                    fmaf(ov[4*g+3], 0.5f, 0.5f));
            }
        }

        __syncthreads();   // protect s_v before next chunk's stores
    }
}

extern "C" void kernel_launch(void* const* d_in, const int* in_sizes, int n_in,
                              void* d_out, int out_size) {
    const float* x = (const float*)d_in[0];
    float* out = (float*)d_out;
    dim3 grid(H / ROWSPB, 96);   // 4 x 96 = 384 blocks
    erode18_kernel<<<grid, NTHREADS>>>(x, out);
}

// round 4
// speedup vs baseline: 1.5271x; 1.5271x over previous
#include <cuda_runtime.h>
#include <cuda_bf16.h>

// Erosion (min filter) k=18, SAME (pad_lo=8, pad_hi=9), on y = x*0.5+0.5.
// NCHW (32,3,512,512) fp32 = 96 planes of 512x512.
//
// Horizontal-first fused separable min filter:
//  Phase A: warp-per-row. Lane owns 4 contiguous cols (float4) -> fully
//    coalesced LDG.128 + STS.128. The 18-wide window (lanes l-2..l+3) is
//    built from per-lane prefix/suffix mins via 10 wrap-shuffles per 128-col
//    round; prev/next-round hybrid values handle round borders; +inf at
//    image borders. 49 h-min rows (TY+17) written to smem.
//  Phase B: thread-per-column. 66 conflict-free scalar LDS, two 16-chunk
//    van Herk sweeps in registers, perfectly coalesced STG.32 stores.
//  One barrier. 0.5x+0.5 (monotone) applied once at the store.

#define W 512
#define H 512
#define TY 32
#define HROWS (TY + 17)            // 49 horizontal-result rows
#define NTHREADS 512
#define SMEM_BYTES (HROWS * W * 4) // 100,352 B

__global__ __launch_bounds__(NTHREADS, 2)
void erode18_kernel(const float* __restrict__ x, float* __restrict__ out) {
    extern __shared__ float s_h[];  // [HROWS][W]

    const int tid  = threadIdx.x;
    const int lane = tid & 31;
    const int warp = tid >> 5;
    const int rowBase = blockIdx.x * TY;
    const long plane = (long)blockIdx.y * (W * H);
    const float INF = __int_as_float(0x7f800000);
    const unsigned FULL = 0xFFFFFFFFu;

    // ================= Phase A: horizontal min-18, warp-per-row =================
    for (int r = warp; r < HROWS; r += 16) {
        const int gr = rowBase - 8 + r;
        const bool inb = (unsigned)gr < (unsigned)H;
        const float4* rowp = (const float4*)(x + plane + (long)gr * W);

        float4 v = inb ? __ldg(rowp + lane)
                       : make_float4(INF, INF, INF, INF);
        // prev-round carries (cols < 0 are +inf for round 0)
        float pS0 = INF, pS1 = INF, pS2 = INF, pS3 = INF, pF = INF;

        float4* orow = (float4*)(s_h + r * W);

        #pragma unroll
        for (int j = 0; j < 4; ++j) {
            float4 vn = (j < 3 && inb) ? __ldg(rowp + 32 * (j + 1) + lane)
                                       : make_float4(INF, INF, INF, INF);
            // own prefix/suffix mins over v (taps = 4 cols)
            float P1 = fminf(v.x, v.y);
            float P2 = fminf(P1, v.z);
            float F  = fminf(P2, v.w);           // full min = P3 = S0
            float S2 = fminf(v.z, v.w);
            float S1 = fminf(v.y, S2);
            // next-round prefixes
            float Pn1 = fminf(vn.x, vn.y);
            float Pn2 = fminf(Pn1, vn.z);
            float Fn  = fminf(Pn2, vn.w);

            // up-shuffles: src = lane-2 (wrap); wrap sources 30,31 export prev round
            float eS0 = (lane >= 30) ? pS0 : F;
            float eS1 = (lane >= 30) ? pS1 : S1;
            float eS2 = (lane >= 30) ? pS2 : S2;
            float eS3 = (lane >= 30) ? pS3 : v.w;
            float u0 = __shfl_sync(FULL, eS0, (lane + 30) & 31);
            float u1 = __shfl_sync(FULL, eS1, (lane + 30) & 31);
            float u2 = __shfl_sync(FULL, eS2, (lane + 30) & 31);
            float u3 = __shfl_sync(FULL, eS3, (lane + 30) & 31);
            // F from lane-1 (wrap source 31 exports prev round)
            float eFu = (lane == 31) ? pF : F;
            float fu = __shfl_sync(FULL, eFu, (lane + 31) & 31);
            // F from lane+1 (wrap source 0 exports next round)
            float eFd = (lane == 0) ? Fn : F;
            float fd = __shfl_sync(FULL, eFd, (lane + 1) & 31);
            // prefixes from lane+2 (wrap sources 0,1 export next round)
            float eP1 = (lane <= 1) ? Pn1 : P1;
            float eP2 = (lane <= 1) ? Pn2 : P2;
            float eP3 = (lane <= 1) ? Fn  : F;
            float d1 = __shfl_sync(FULL, eP1, (lane + 2) & 31);
            float d2 = __shfl_sync(FULL, eP2, (lane + 2) & 31);
            float d3 = __shfl_sync(FULL, eP3, (lane + 2) & 31);
            // v.x from lane+3 (wrap sources 0..2 export next round)
            float evx = (lane <= 2) ? vn.x : v.x;
            float dx = __shfl_sync(FULL, evx, (lane + 3) & 31);

            float core = fminf(fminf(fu, F), fd);   // lanes l-1, l, l+1 (12 cols)
            float4 ov;
            ov.x = fminf(fminf(u0, core), d1);             // window [-8, +9]
            ov.y = fminf(fminf(u1, core), d2);
            ov.z = fminf(fminf(u2, core), d3);
            ov.w = fminf(fminf(u3, core), fminf(d3, dx));
            orow[32 * j + lane] = ov;

            pS0 = F; pS1 = S1; pS2 = S2; pS3 = v.w; pF = F;
            v = vn;
        }
    }
    __syncthreads();

    // ============== Phase B: vertical min-18, thread-per-column ==============
    {
        const float* cp = s_h + tid;            // column tid
        float* op = out + plane + (long)rowBase * W + tid;
        float S[16];

        // chunk A: output rows 0..15, taps 0..32 (smem rows)
        {
            float s = cp[17 * W];
            #pragma unroll
            for (int i = 16; i >= 0; --i) {
                s = fminf(s, cp[i * W]);
                if (i <= 15) S[i] = s;
            }
        }
        op[0] = fmaf(S[0], 0.5f, 0.5f);
        {
            float p = cp[18 * W];
            op[W] = fmaf(fminf(S[1], p), 0.5f, 0.5f);
            #pragma unroll
            for (int o = 2; o <= 15; ++o) {
                p = fminf(p, cp[(o + 17) * W]);
                op[(long)o * W] = fmaf(fminf(S[o], p), 0.5f, 0.5f);
            }
        }

        // chunk B: output rows 16..31, taps 16..48
        op = out + plane + (long)(rowBase + 16) * W + tid;
        {
            float s = cp[33 * W];
            #pragma unroll
            for (int i = 32; i >= 16; --i) {
                s = fminf(s, cp[i * W]);
                if (i <= 31) S[i - 16] = s;
            }
        }
        op[0] = fmaf(S[0], 0.5f, 0.5f);
        {
            float p = cp[34 * W];
            op[W] = fmaf(fminf(S[1], p), 0.5f, 0.5f);
            #pragma unroll
            for (int o = 2; o <= 15; ++o) {
                p = fminf(p, cp[(o + 33) * W]);
                op[(long)o * W] = fmaf(fminf(S[o], p), 0.5f, 0.5f);
            }
        }
    }
}

extern "C" void kernel_launch(void* const* d_in, const int* in_sizes, int n_in,
                              void* d_out, int out_size) {
    const float* x = (const float*)d_in[0];
    float* out = (float*)d_out;

    // Idempotent host-side attribute set; not part of graph capture.
    cudaFuncSetAttribute(erode18_kernel,
                         cudaFuncAttributeMaxDynamicSharedMemorySize, SMEM_BYTES);

    dim3 grid(H / TY, 96);   // 16 x 96 = 1536 blocks
    erode18_kernel<<<grid, NTHREADS, SMEM_BYTES>>>(x, out);
}